// round 8
// baseline (speedup 1.0000x reference)
#include <cuda_runtime.h>
#include <cstdint>

// ============================================================
// Problem constants
// ============================================================
#define MDIM 32768
#define KDIM 1024
#define NDIM 1024

static constexpr int BM = 128;
static constexpr int BN = 128;
static constexpr int BK = 64;              // K bytes per stage
static constexpr int STAGES = 4;
static constexpr int KITERS = KDIM / BK;   // 16
static constexpr int THREADS = 256;

// padded smem rows: 64 data bytes padded to 80 (16B aligned, conflict-free LDS.32)
static constexpr int ROWB = 80;
static constexpr int A_STG = BM * ROWB;            // 10240
static constexpr int B_STG = BN * ROWB;            // 10240
static constexpr int STAGE_BYTES = A_STG + B_STG;  // 20480
static constexpr int SM_ALPHA = 0;                 // 128 floats
static constexpr int SM_BETA  = 512;               // 128 floats
static constexpr int SM_TILES = 1024;
static constexpr int SMEM_TOTAL = SM_TILES + STAGES * STAGE_BYTES;  // 82944

// ============================================================
// Device scratch (no allocations allowed)
// ============================================================
__device__ __align__(1024) signed char g_xq[(size_t)MDIM * KDIM];   // 32 MB
__device__ __align__(1024) signed char g_wt[(size_t)NDIM * KDIM];   // 1 MB, w transposed [N,K]
__device__ float g_alpha[NDIM];
__device__ float g_beta[NDIM];
__device__ float g_pmin[2048];
__device__ float g_pmax[2048];
__device__ float g_inv_scale;
__device__ float g_zp;
__device__ int   g_w_mode;   // 0 = int8 storage, 1 = int32 storage, 2 = float32 storage

// ============================================================
// PTX helpers (baseline ISA only — harness targets compute_103, no tcgen05/TMA)
// ============================================================
__device__ __forceinline__ uint32_t smem_u32(const void* p) {
    uint32_t a;
    asm("{ .reg .u64 t; cvta.to.shared.u64 t, %1; cvt.u32.u64 %0, t; }"
        : "=r"(a) : "l"(p));
    return a;
}

__device__ __forceinline__ void cp_async16(uint32_t dst, const void* src) {
    asm volatile("cp.async.cg.shared.global [%0], [%1], 16;"
                 :: "r"(dst), "l"(src) : "memory");
}
__device__ __forceinline__ void cp_async_commit() {
    asm volatile("cp.async.commit_group;" ::: "memory");
}
template <int N>
__device__ __forceinline__ void cp_async_wait() {
    asm volatile("cp.async.wait_group %0;" :: "n"(N) : "memory");
}

__device__ __forceinline__ uint32_t lds32(uint32_t addr) {
    uint32_t v;
    asm volatile("ld.shared.b32 %0, [%1];" : "=r"(v) : "r"(addr));
    return v;
}

__device__ __forceinline__ void mma_s8(int* c, const uint32_t* a, const uint32_t* b) {
    asm volatile(
        "mma.sync.aligned.m16n8k32.row.col.s32.s8.s8.s32 "
        "{%0,%1,%2,%3}, {%4,%5,%6,%7}, {%8,%9}, {%0,%1,%2,%3};"
        : "+r"(c[0]), "+r"(c[1]), "+r"(c[2]), "+r"(c[3])
        : "r"(a[0]), "r"(a[1]), "r"(a[2]), "r"(a[3]), "r"(b[0]), "r"(b[1]));
}

// ============================================================
// Kernel 0: probe the storage dtype of the int8 weight tensor.
// The harness may promote int8 inputs to int32 or float32 on upload.
//  - int32 storage: every word is a value in [-128, 127].
//  - float32 storage: every word, as float, is integral in [-128, 127].
//  - otherwise: genuine packed int8 bytes.
// Inspecting 4096 words makes misclassification probability ~0
// (a random int8 byte-pack word is in [-128,127] with p ~ 2^-24).
// ============================================================
__global__ void __launch_bounds__(256) k_probe_w(const int* __restrict__ w) {
    __shared__ int s_i32_ok, s_f32_ok;
    if (threadIdx.x == 0) { s_i32_ok = 1; s_f32_ok = 1; }
    __syncthreads();
    int i32_ok = 1, f32_ok = 1;
    for (int i = threadIdx.x; i < 4096; i += 256) {
        int v = w[i];
        if (v < -128 || v > 127) i32_ok = 0;
        float f = __int_as_float(v);
        if (!(f >= -128.0f && f <= 127.0f && rintf(f) == f)) f32_ok = 0;
    }
    if (!i32_ok) atomicAnd(&s_i32_ok, 0);
    if (!f32_ok) atomicAnd(&s_f32_ok, 0);
    __syncthreads();
    if (threadIdx.x == 0)
        g_w_mode = s_i32_ok ? 1 : (s_f32_ok ? 2 : 0);
}

// ============================================================
// Kernel 1: per-block min/max partials over x
// ============================================================
__global__ void __launch_bounds__(256) k_minmax(const float4* __restrict__ x, int n4) {
    __shared__ float smin[256], smax[256];
    int tid = threadIdx.x;
    float mn = 0.0f, mx = 0.0f;  // min(.,0)/max(.,0) clamp folded in
    for (int i = blockIdx.x * 256 + tid; i < n4; i += 2048 * 256) {
        float4 v = x[i];
        mn = fminf(mn, fminf(fminf(v.x, v.y), fminf(v.z, v.w)));
        mx = fmaxf(mx, fmaxf(fmaxf(v.x, v.y), fmaxf(v.z, v.w)));
    }
    smin[tid] = mn; smax[tid] = mx;
    __syncthreads();
    for (int off = 128; off > 0; off >>= 1) {
        if (tid < off) {
            smin[tid] = fminf(smin[tid], smin[tid + off]);
            smax[tid] = fmaxf(smax[tid], smax[tid + off]);
        }
        __syncthreads();
    }
    if (tid == 0) { g_pmin[blockIdx.x] = smin[0]; g_pmax[blockIdx.x] = smax[0]; }
}

// ============================================================
// Kernel 2: transpose w [K,N] -> g_wt [N,K] (dtype-agnostic read)
// ============================================================
__global__ void __launch_bounds__(256) k_transpose(const void* __restrict__ wraw) {
    __shared__ signed char t[32][33];
    const signed char* w8  = (const signed char*)wraw;
    const int*         w32 = (const int*)wraw;
    const float*       wf  = (const float*)wraw;
    int mode = g_w_mode;
    int tx = threadIdx.x, ty = threadIdx.y;
    int n0 = blockIdx.x * 32, k0 = blockIdx.y * 32;
    #pragma unroll
    for (int i = ty; i < 32; i += 8) {
        size_t idx = (size_t)(k0 + i) * NDIM + n0 + tx;
        signed char v;
        if (mode == 1)      v = (signed char)w32[idx];
        else if (mode == 2) v = (signed char)(int)wf[idx];
        else                v = w8[idx];
        t[i][tx] = v;
    }
    __syncthreads();
    #pragma unroll
    for (int i = ty; i < 32; i += 8)
        g_wt[(size_t)(n0 + i) * KDIM + k0 + tx] = t[tx][i];
}

// ============================================================
// Kernel 3: reduce -> scale/zp + fused epilogue coefficients
// ============================================================
__global__ void __launch_bounds__(1024) k_scalars(const float* __restrict__ wsc,
                                                  const int* __restrict__ sums,
                                                  const float* __restrict__ bias) {
    __shared__ float smin[1024], smax[1024];
    __shared__ float s_scale, s_zp;
    int tid = threadIdx.x;
    smin[tid] = fminf(g_pmin[tid], g_pmin[tid + 1024]);
    smax[tid] = fmaxf(g_pmax[tid], g_pmax[tid + 1024]);
    __syncthreads();
    for (int off = 512; off > 0; off >>= 1) {
        if (tid < off) {
            smin[tid] = fminf(smin[tid], smin[tid + off]);
            smax[tid] = fmaxf(smax[tid], smax[tid + off]);
        }
        __syncthreads();
    }
    if (tid == 0) {
        const float EPSV = 1.1920928955078125e-07f;  // np.finfo(float32).eps
        float mn = smin[0], mx = smax[0];
        float scale = fmaxf((mx - mn) / 255.0f, EPSV);
        float zp = -128.0f - rintf(mn / scale);      // rintf == round-half-even
        zp = fminf(fmaxf(zp, -128.0f), 127.0f);
        s_scale = scale;
        s_zp = zp;
        g_inv_scale = 1.0f / scale;
        g_zp = zp;
    }
    __syncthreads();
    float alpha = s_scale * wsc[tid];
    g_alpha[tid] = alpha;
    g_beta[tid]  = fmaf(-alpha * s_zp, (float)sums[tid], bias[tid]);
}

// ============================================================
// Kernel 4: quantize x -> g_xq (int8)
// ============================================================
__global__ void __launch_bounds__(256) k_quant(const float4* __restrict__ x,
                                               char4* __restrict__ xq, int n4) {
    float inv = g_inv_scale;
    float zp  = g_zp;
    for (int i = blockIdx.x * 256 + threadIdx.x; i < n4; i += 2048 * 256) {
        float4 v = x[i];
        float a = fminf(fmaxf(rintf(v.x * inv) + zp, -128.0f), 127.0f);
        float b = fminf(fmaxf(rintf(v.y * inv) + zp, -128.0f), 127.0f);
        float c = fminf(fmaxf(rintf(v.z * inv) + zp, -128.0f), 127.0f);
        float d = fminf(fmaxf(rintf(v.w * inv) + zp, -128.0f), 127.0f);
        char4 q;
        q.x = (signed char)(int)a;
        q.y = (signed char)(int)b;
        q.z = (signed char)(int)c;
        q.w = (signed char)(int)d;
        xq[i] = q;
    }
}

// ============================================================
// Kernel 5: int8 IMMA GEMM (mma.sync m16n8k32) + fused dequant epilogue
//   8 warps: 2 (M) x 4 (N); warp tile 64x32; cp.async 4-stage pipeline
// ============================================================
__device__ __forceinline__ void load_stage(uint32_t sb, int s, int m0, int n0, int k0) {
    uint32_t base = sb + SM_TILES + s * STAGE_BYTES;
    int t = threadIdx.x;
    #pragma unroll
    for (int h = 0; h < 2; ++h) {
        int cc = t + h * 256;              // 0..511 chunk id
        int row = cc >> 2, kw = cc & 3;    // 128 rows x 4 x 16B
        cp_async16(base + row * ROWB + kw * 16,
                   g_xq + (size_t)(m0 + row) * KDIM + k0 + kw * 16);
    }
    #pragma unroll
    for (int h = 0; h < 2; ++h) {
        int cc = t + h * 256;
        int row = cc >> 2, kw = cc & 3;
        cp_async16(base + A_STG + row * ROWB + kw * 16,
                   g_wt + (size_t)(n0 + row) * KDIM + k0 + kw * 16);
    }
}

__global__ void __launch_bounds__(THREADS, 2) gemm_k(float* __restrict__ out) {
    extern __shared__ char smem[];
    uint32_t sb = smem_u32(smem);
    int tid = threadIdx.x, wid = tid >> 5, lane = tid & 31;
    int warpM = wid >> 2;             // 0..1  (64 rows each)
    int warpN = wid & 3;              // 0..3  (32 cols each)
    int ntile = blockIdx.x & 7;
    int mtile = blockIdx.x >> 3;
    int m0 = mtile * BM, n0 = ntile * BN;

    // cache epilogue coefficients
    float* aS = (float*)(smem + SM_ALPHA);
    float* bS = (float*)(smem + SM_BETA);
    for (int i = tid; i < BN; i += THREADS) {
        aS[i] = g_alpha[n0 + i];
        bS[i] = g_beta[n0 + i];
    }

    // prologue: fill STAGES-1 stages
    #pragma unroll
    for (int st = 0; st < STAGES - 1; ++st) {
        load_stage(sb, st, m0, n0, st * BK);
        cp_async_commit();
    }

    int acc[4][4][4];
    #pragma unroll
    for (int mt = 0; mt < 4; ++mt)
        #pragma unroll
        for (int nt = 0; nt < 4; ++nt)
            #pragma unroll
            for (int r = 0; r < 4; ++r)
                acc[mt][nt][r] = 0;

    int g = lane >> 2;                 // groupID 0..7
    int q = lane & 3;                  // threadID_in_group 0..3

    for (int it = 0; it < KITERS; ++it) {
        cp_async_wait<STAGES - 2>();
        __syncthreads();
        int s = it & (STAGES - 1);
        uint32_t a_base = sb + SM_TILES + s * STAGE_BYTES + (warpM * 64) * ROWB;
        uint32_t b_base = sb + SM_TILES + s * STAGE_BYTES + A_STG + (warpN * 32) * ROWB;

        #pragma unroll
        for (int kk = 0; kk < 2; ++kk) {       // two k32 slabs per BK=64
            int ko = kk * 32 + q * 4;
            uint32_t afr[4][4];
            #pragma unroll
            for (int mt = 0; mt < 4; ++mt) {
                uint32_t ad = a_base + (mt * 16 + g) * ROWB + ko;
                afr[mt][0] = lds32(ad);                 // row g,   k lo
                afr[mt][1] = lds32(ad + 8 * ROWB);      // row g+8, k lo
                afr[mt][2] = lds32(ad + 16);            // row g,   k hi
                afr[mt][3] = lds32(ad + 8 * ROWB + 16); // row g+8, k hi
            }
            uint32_t bfr[4][2];
            #pragma unroll
            for (int nt = 0; nt < 4; ++nt) {
                uint32_t bd = b_base + (nt * 8 + g) * ROWB + ko;
                bfr[nt][0] = lds32(bd);                 // col g, k lo
                bfr[nt][1] = lds32(bd + 16);            // col g, k hi
            }
            #pragma unroll
            for (int mt = 0; mt < 4; ++mt)
                #pragma unroll
                for (int nt = 0; nt < 4; ++nt)
                    mma_s8(acc[mt][nt], afr[mt], bfr[nt]);
        }

        if (it + STAGES - 1 < KITERS)
            load_stage(sb, (it + STAGES - 1) & (STAGES - 1), m0, n0,
                       (it + STAGES - 1) * BK);
        cp_async_commit();   // commit (possibly empty) to keep group counting uniform
    }

    // ---- epilogue: y = alpha[n]*acc + beta[n] ----
    #pragma unroll
    for (int mt = 0; mt < 4; ++mt) {
        int r0 = m0 + warpM * 64 + mt * 16 + g;
        float* out0 = out + (size_t)r0 * NDIM;
        float* out1 = out0 + (size_t)8 * NDIM;
        #pragma unroll
        for (int nt = 0; nt < 4; ++nt) {
            int cco = warpN * 32 + nt * 8 + q * 2;   // col within block
            int col = n0 + cco;
            float a0 = aS[cco], a1 = aS[cco + 1];
            float b0 = bS[cco], b1 = bS[cco + 1];
            float2 v0, v1;
            v0.x = fmaf((float)acc[mt][nt][0], a0, b0);
            v0.y = fmaf((float)acc[mt][nt][1], a1, b1);
            v1.x = fmaf((float)acc[mt][nt][2], a0, b0);
            v1.y = fmaf((float)acc[mt][nt][3], a1, b1);
            *(float2*)(out0 + col) = v0;
            *(float2*)(out1 + col) = v1;
        }
    }
}

// ============================================================
// Host launch
// ============================================================
extern "C" void kernel_launch(void* const* d_in, const int* in_sizes, int n_in,
                              void* d_out, int out_size) {
    const float* x    = (const float*)d_in[0];
    const void*  w    = d_in[1];
    const float* wsc  = (const float*)d_in[2];
    const int*   sums = (const int*)d_in[3];
    const float* bias = (const float*)d_in[4];
    float*       out  = (float*)d_out;

    cudaFuncSetAttribute(gemm_k, cudaFuncAttributeMaxDynamicSharedMemorySize,
                         SMEM_TOTAL);

    void* xq_ptr = nullptr;
    cudaGetSymbolAddress(&xq_ptr, g_xq);

    int n4 = (MDIM * KDIM) / 4;
    k_probe_w<<<1, 256>>>((const int*)w);
    k_minmax<<<2048, 256>>>((const float4*)x, n4);
    k_transpose<<<dim3(NDIM / 32, KDIM / 32), dim3(32, 8)>>>(w);
    k_scalars<<<1, 1024>>>(wsc, sums, bias);
    k_quant<<<2048, 256>>>((const float4*)x, (char4*)xq_ptr, n4);
    gemm_k<<<(MDIM / BM) * (NDIM / BN), THREADS, SMEM_TOTAL>>>(out);
}

// round 10
// speedup vs baseline: 1.5717x; 1.5717x over previous
#include <cuda_runtime.h>
#include <cstdint>

// ============================================================
// Problem constants
// ============================================================
#define MDIM 32768
#define KDIM 1024
#define NDIM 1024

static constexpr int BM = 128;
static constexpr int BN = 128;
static constexpr int BK = 64;              // K bytes per stage
static constexpr int STAGES = 4;
static constexpr int KITERS = KDIM / BK;   // 16
static constexpr int THREADS = 256;

// padded smem rows: 64 data bytes padded to 80 (16B aligned, conflict-free LDS.32)
static constexpr int ROWB = 80;
static constexpr int A_STG = BM * ROWB;            // 10240
static constexpr int B_STG = BN * ROWB;            // 10240
static constexpr int STAGE_BYTES = A_STG + B_STG;  // 20480
static constexpr int SM_ALPHA = 0;                 // 128 floats
static constexpr int SM_BETA  = 512;               // 128 floats
static constexpr int SM_TILES = 1024;
static constexpr int SMEM_TOTAL = SM_TILES + STAGES * STAGE_BYTES;  // 82944

// ============================================================
// Device scratch (no allocations allowed)
// ============================================================
__device__ __align__(1024) signed char g_xq[(size_t)MDIM * KDIM];   // 32 MB
__device__ __align__(1024) signed char g_wt[(size_t)NDIM * KDIM];   // 1 MB, w transposed [N,K]
__device__ float g_alpha[NDIM];
__device__ float g_beta[NDIM];
__device__ float g_pmin[2048];
__device__ float g_pmax[2048];
__device__ float g_inv_scale;
__device__ float g_zp;
__device__ int   g_w_mode;   // 0 = int8 storage, 1 = int32 storage, 2 = float32 storage

// ============================================================
// PTX helpers (baseline ISA only — harness targets compute_103, no tcgen05/TMA)
// ============================================================
__device__ __forceinline__ uint32_t smem_u32(const void* p) {
    uint32_t a;
    asm("{ .reg .u64 t; cvta.to.shared.u64 t, %1; cvt.u32.u64 %0, t; }"
        : "=r"(a) : "l"(p));
    return a;
}

__device__ __forceinline__ void cp_async16(uint32_t dst, const void* src) {
    asm volatile("cp.async.cg.shared.global [%0], [%1], 16;"
                 :: "r"(dst), "l"(src) : "memory");
}
__device__ __forceinline__ void cp_async_commit() {
    asm volatile("cp.async.commit_group;" ::: "memory");
}
template <int N>
__device__ __forceinline__ void cp_async_wait() {
    asm volatile("cp.async.wait_group %0;" :: "n"(N) : "memory");
}

__device__ __forceinline__ uint32_t lds32(uint32_t addr) {
    uint32_t v;
    asm volatile("ld.shared.b32 %0, [%1];" : "=r"(v) : "r"(addr));
    return v;
}

__device__ __forceinline__ void mma_s8(int* c, const uint32_t* a, const uint32_t* b) {
    asm volatile(
        "mma.sync.aligned.m16n8k32.row.col.s32.s8.s8.s32 "
        "{%0,%1,%2,%3}, {%4,%5,%6,%7}, {%8,%9}, {%0,%1,%2,%3};"
        : "+r"(c[0]), "+r"(c[1]), "+r"(c[2]), "+r"(c[3])
        : "r"(a[0]), "r"(a[1]), "r"(a[2]), "r"(a[3]), "r"(b[0]), "r"(b[1]));
}

// ============================================================
// Kernel 0: probe the storage dtype of the int8 weight tensor.
// The harness may promote int8 inputs to int32 or float32 on upload.
// ============================================================
__global__ void __launch_bounds__(256) k_probe_w(const int* __restrict__ w) {
    __shared__ int s_i32_ok, s_f32_ok;
    if (threadIdx.x == 0) { s_i32_ok = 1; s_f32_ok = 1; }
    __syncthreads();
    int i32_ok = 1, f32_ok = 1;
    for (int i = threadIdx.x; i < 4096; i += 256) {
        int v = w[i];
        if (v < -128 || v > 127) i32_ok = 0;
        float f = __int_as_float(v);
        if (!(f >= -128.0f && f <= 127.0f && rintf(f) == f)) f32_ok = 0;
    }
    if (!i32_ok) atomicAnd(&s_i32_ok, 0);
    if (!f32_ok) atomicAnd(&s_f32_ok, 0);
    __syncthreads();
    if (threadIdx.x == 0)
        g_w_mode = s_i32_ok ? 1 : (s_f32_ok ? 2 : 0);
}

// ============================================================
// Kernel 1: per-block min/max partials over x
// ============================================================
__global__ void __launch_bounds__(256) k_minmax(const float4* __restrict__ x, int n4) {
    __shared__ float smin[256], smax[256];
    int tid = threadIdx.x;
    float mn = 0.0f, mx = 0.0f;  // min(.,0)/max(.,0) clamp folded in
    for (int i = blockIdx.x * 256 + tid; i < n4; i += 2048 * 256) {
        float4 v = x[i];
        mn = fminf(mn, fminf(fminf(v.x, v.y), fminf(v.z, v.w)));
        mx = fmaxf(mx, fmaxf(fmaxf(v.x, v.y), fmaxf(v.z, v.w)));
    }
    smin[tid] = mn; smax[tid] = mx;
    __syncthreads();
    for (int off = 128; off > 0; off >>= 1) {
        if (tid < off) {
            smin[tid] = fminf(smin[tid], smin[tid + off]);
            smax[tid] = fmaxf(smax[tid], smax[tid + off]);
        }
        __syncthreads();
    }
    if (tid == 0) { g_pmin[blockIdx.x] = smin[0]; g_pmax[blockIdx.x] = smax[0]; }
}

// ============================================================
// Kernel 2: transpose w [K,N] -> g_wt [N,K] (dtype-agnostic read)
// ============================================================
__global__ void __launch_bounds__(256) k_transpose(const void* __restrict__ wraw) {
    __shared__ signed char t[32][33];
    const signed char* w8  = (const signed char*)wraw;
    const int*         w32 = (const int*)wraw;
    const float*       wf  = (const float*)wraw;
    int mode = g_w_mode;
    int tx = threadIdx.x, ty = threadIdx.y;
    int n0 = blockIdx.x * 32, k0 = blockIdx.y * 32;
    #pragma unroll
    for (int i = ty; i < 32; i += 8) {
        size_t idx = (size_t)(k0 + i) * NDIM + n0 + tx;
        signed char v;
        if (mode == 1)      v = (signed char)w32[idx];
        else if (mode == 2) v = (signed char)(int)wf[idx];
        else                v = w8[idx];
        t[i][tx] = v;
    }
    __syncthreads();
    #pragma unroll
    for (int i = ty; i < 32; i += 8)
        g_wt[(size_t)(n0 + i) * KDIM + k0 + tx] = t[tx][i];
}

// ============================================================
// Kernel 3: reduce -> scale/zp + fused epilogue coefficients
// ============================================================
__global__ void __launch_bounds__(1024) k_scalars(const float* __restrict__ wsc,
                                                  const int* __restrict__ sums,
                                                  const float* __restrict__ bias) {
    __shared__ float smin[1024], smax[1024];
    __shared__ float s_scale, s_zp;
    int tid = threadIdx.x;
    smin[tid] = fminf(g_pmin[tid], g_pmin[tid + 1024]);
    smax[tid] = fmaxf(g_pmax[tid], g_pmax[tid + 1024]);
    __syncthreads();
    for (int off = 512; off > 0; off >>= 1) {
        if (tid < off) {
            smin[tid] = fminf(smin[tid], smin[tid + off]);
            smax[tid] = fmaxf(smax[tid], smax[tid + off]);
        }
        __syncthreads();
    }
    if (tid == 0) {
        const float EPSV = 1.1920928955078125e-07f;  // np.finfo(float32).eps
        float mn = smin[0], mx = smax[0];
        float scale = fmaxf((mx - mn) / 255.0f, EPSV);
        float zp = -128.0f - rintf(mn / scale);      // rintf == round-half-even
        zp = fminf(fmaxf(zp, -128.0f), 127.0f);
        s_scale = scale;
        s_zp = zp;
        g_inv_scale = 1.0f / scale;
        g_zp = zp;
    }
    __syncthreads();
    float alpha = s_scale * wsc[tid];
    g_alpha[tid] = alpha;
    g_beta[tid]  = fmaf(-alpha * s_zp, (float)sums[tid], bias[tid]);
}

// ============================================================
// Kernel 4: quantize x -> g_xq (int8)
// ============================================================
__global__ void __launch_bounds__(256) k_quant(const float4* __restrict__ x,
                                               char4* __restrict__ xq, int n4) {
    float inv = g_inv_scale;
    float zp  = g_zp;
    for (int i = blockIdx.x * 256 + threadIdx.x; i < n4; i += 2048 * 256) {
        float4 v = x[i];
        float a = fminf(fmaxf(rintf(v.x * inv) + zp, -128.0f), 127.0f);
        float b = fminf(fmaxf(rintf(v.y * inv) + zp, -128.0f), 127.0f);
        float c = fminf(fmaxf(rintf(v.z * inv) + zp, -128.0f), 127.0f);
        float d = fminf(fmaxf(rintf(v.w * inv) + zp, -128.0f), 127.0f);
        char4 q;
        q.x = (signed char)(int)a;
        q.y = (signed char)(int)b;
        q.z = (signed char)(int)c;
        q.w = (signed char)(int)d;
        xq[i] = q;
    }
}

// ============================================================
// Kernel 5: int8 IMMA GEMM (mma.sync m16n8k32) + fused dequant epilogue
//   8 warps: 2 (M) x 4 (N); warp tile 64x32; cp.async 4-stage pipeline
//   Register-lean inner loop: B fragments (8 regs) live per k-slab; A
//   fragments (4 regs) loaded per mt and consumed immediately.
//   Live set ~= acc(64) + bfr(8) + af(4) + addressing => fits 128-reg
//   cap at 2 CTAs/SM WITHOUT spills (the R8 version spilled).
// ============================================================
__device__ __forceinline__ void load_stage(uint32_t sb, int s, int m0, int n0, int k0) {
    uint32_t base = sb + SM_TILES + s * STAGE_BYTES;
    int t = threadIdx.x;
    #pragma unroll
    for (int h = 0; h < 2; ++h) {
        int cc = t + h * 256;              // 0..511 chunk id
        int row = cc >> 2, kw = cc & 3;    // 128 rows x 4 x 16B
        cp_async16(base + row * ROWB + kw * 16,
                   g_xq + (size_t)(m0 + row) * KDIM + k0 + kw * 16);
    }
    #pragma unroll
    for (int h = 0; h < 2; ++h) {
        int cc = t + h * 256;
        int row = cc >> 2, kw = cc & 3;
        cp_async16(base + A_STG + row * ROWB + kw * 16,
                   g_wt + (size_t)(n0 + row) * KDIM + k0 + kw * 16);
    }
}

__global__ void __launch_bounds__(THREADS, 2) gemm_k(float* __restrict__ out) {
    extern __shared__ char smem[];
    uint32_t sb = smem_u32(smem);
    int tid = threadIdx.x, wid = tid >> 5, lane = tid & 31;
    int warpM = wid >> 2;             // 0..1  (64 rows each)
    int warpN = wid & 3;              // 0..3  (32 cols each)
    int ntile = blockIdx.x & 7;
    int mtile = blockIdx.x >> 3;
    int m0 = mtile * BM, n0 = ntile * BN;

    // cache epilogue coefficients
    float* aS = (float*)(smem + SM_ALPHA);
    float* bS = (float*)(smem + SM_BETA);
    for (int i = tid; i < BN; i += THREADS) {
        aS[i] = g_alpha[n0 + i];
        bS[i] = g_beta[n0 + i];
    }

    // prologue: fill STAGES-1 stages
    #pragma unroll
    for (int st = 0; st < STAGES - 1; ++st) {
        load_stage(sb, st, m0, n0, st * BK);
        cp_async_commit();
    }

    int acc[4][4][4];
    #pragma unroll
    for (int mt = 0; mt < 4; ++mt)
        #pragma unroll
        for (int nt = 0; nt < 4; ++nt)
            #pragma unroll
            for (int r = 0; r < 4; ++r)
                acc[mt][nt][r] = 0;

    int g = lane >> 2;                 // groupID 0..7
    int q = lane & 3;                  // threadID_in_group 0..3

    for (int it = 0; it < KITERS; ++it) {
        cp_async_wait<STAGES - 2>();
        __syncthreads();
        int s = it & (STAGES - 1);
        uint32_t a_base = sb + SM_TILES + s * STAGE_BYTES + (warpM * 64) * ROWB;
        uint32_t b_base = sb + SM_TILES + s * STAGE_BYTES + A_STG + (warpN * 32) * ROWB;

        #pragma unroll
        for (int kk = 0; kk < 2; ++kk) {       // two k32 slabs per BK=64
            int ko = kk * 32 + q * 4;
            uint32_t bfr[4][2];
            #pragma unroll
            for (int nt = 0; nt < 4; ++nt) {
                uint32_t bd = b_base + (nt * 8 + g) * ROWB + ko;
                bfr[nt][0] = lds32(bd);                 // col g, k lo
                bfr[nt][1] = lds32(bd + 16);            // col g, k hi
            }
            #pragma unroll
            for (int mt = 0; mt < 4; ++mt) {
                uint32_t ad = a_base + (mt * 16 + g) * ROWB + ko;
                uint32_t af[4];
                af[0] = lds32(ad);                      // row g,   k lo
                af[1] = lds32(ad + 8 * ROWB);           // row g+8, k lo
                af[2] = lds32(ad + 16);                 // row g,   k hi
                af[3] = lds32(ad + 8 * ROWB + 16);      // row g+8, k hi
                #pragma unroll
                for (int nt = 0; nt < 4; ++nt)
                    mma_s8(acc[mt][nt], af, bfr[nt]);
            }
        }

        if (it + STAGES - 1 < KITERS)
            load_stage(sb, (it + STAGES - 1) & (STAGES - 1), m0, n0,
                       (it + STAGES - 1) * BK);
        cp_async_commit();   // commit (possibly empty) to keep group counting uniform
    }

    // ---- epilogue: y = alpha[n]*acc + beta[n] ----
    #pragma unroll
    for (int mt = 0; mt < 4; ++mt) {
        int r0 = m0 + warpM * 64 + mt * 16 + g;
        float* out0 = out + (size_t)r0 * NDIM;
        float* out1 = out0 + (size_t)8 * NDIM;
        #pragma unroll
        for (int nt = 0; nt < 4; ++nt) {
            int cco = warpN * 32 + nt * 8 + q * 2;   // col within block
            int col = n0 + cco;
            float a0 = aS[cco], a1 = aS[cco + 1];
            float b0 = bS[cco], b1 = bS[cco + 1];
            float2 v0, v1;
            v0.x = fmaf((float)acc[mt][nt][0], a0, b0);
            v0.y = fmaf((float)acc[mt][nt][1], a1, b1);
            v1.x = fmaf((float)acc[mt][nt][2], a0, b0);
            v1.y = fmaf((float)acc[mt][nt][3], a1, b1);
            *(float2*)(out0 + col) = v0;
            *(float2*)(out1 + col) = v1;
        }
    }
}

// ============================================================
// Host launch
// ============================================================
extern "C" void kernel_launch(void* const* d_in, const int* in_sizes, int n_in,
                              void* d_out, int out_size) {
    const float* x    = (const float*)d_in[0];
    const void*  w    = d_in[1];
    const float* wsc  = (const float*)d_in[2];
    const int*   sums = (const int*)d_in[3];
    const float* bias = (const float*)d_in[4];
    float*       out  = (float*)d_out;

    cudaFuncSetAttribute(gemm_k, cudaFuncAttributeMaxDynamicSharedMemorySize,
                         SMEM_TOTAL);

    void* xq_ptr = nullptr;
    cudaGetSymbolAddress(&xq_ptr, g_xq);

    int n4 = (MDIM * KDIM) / 4;
    k_probe_w<<<1, 256>>>((const int*)w);
    k_minmax<<<2048, 256>>>((const float4*)x, n4);
    k_transpose<<<dim3(NDIM / 32, KDIM / 32), dim3(32, 8)>>>(w);
    k_scalars<<<1, 1024>>>(wsc, sums, bias);
    k_quant<<<2048, 256>>>((const float4*)x, (char4*)xq_ptr, n4);
    gemm_k<<<(MDIM / BM) * (NDIM / BN), THREADS, SMEM_TOTAL>>>(out);
}

// round 13
// speedup vs baseline: 3.0009x; 1.9093x over previous
#include <cuda_runtime.h>
#include <cuda_fp16.h>
#include <cstdint>

// ============================================================
// Problem constants
// ============================================================
#define MDIM 32768
#define KDIM 1024
#define NDIM 1024

static constexpr int BM = 128;
static constexpr int BN = 128;
static constexpr int BKE = 32;             // K elements (fp16) per stage = 64 B rows
static constexpr int STAGES = 4;
static constexpr int KITERS = KDIM / BKE;  // 32
static constexpr int THREADS = 256;

// padded smem rows: 64 data bytes padded to 80 (16B aligned, conflict-free LDS.32)
static constexpr int ROWB = 80;
static constexpr int A_STG = BM * ROWB;            // 10240
static constexpr int B_STG = BN * ROWB;            // 10240
static constexpr int STAGE_BYTES = A_STG + B_STG;  // 20480
static constexpr int SM_ALPHA = 0;                 // 128 floats
static constexpr int SM_BETA  = 512;               // 128 floats
static constexpr int SM_TILES = 1024;
static constexpr int SMEM_TOTAL = SM_TILES + STAGES * STAGE_BYTES;  // 82944

// ============================================================
// Device scratch (no allocations allowed)
// ============================================================
__device__ __align__(1024) __half g_xqh[(size_t)MDIM * KDIM];   // 64 MB quantized x (fp16 ints)
__device__ __align__(1024) __half g_wth[(size_t)NDIM * KDIM];   // 2 MB transposed weight [N,K]
__device__ float g_alpha[NDIM];
__device__ float g_beta[NDIM];
__device__ float g_pmin[2048];
__device__ float g_pmax[2048];
__device__ float g_inv_scale;
__device__ float g_zp;
__device__ int   g_w_mode;   // 0 = int8 storage, 1 = int32 storage, 2 = float32 storage

// ============================================================
// PTX helpers (baseline ISA only — harness targets compute_103, no tcgen05/TMA)
// ============================================================
__device__ __forceinline__ uint32_t smem_u32(const void* p) {
    uint32_t a;
    asm("{ .reg .u64 t; cvta.to.shared.u64 t, %1; cvt.u32.u64 %0, t; }"
        : "=r"(a) : "l"(p));
    return a;
}

__device__ __forceinline__ void cp_async16(uint32_t dst, const void* src) {
    asm volatile("cp.async.cg.shared.global [%0], [%1], 16;"
                 :: "r"(dst), "l"(src) : "memory");
}
__device__ __forceinline__ void cp_async_commit() {
    asm volatile("cp.async.commit_group;" ::: "memory");
}
template <int N>
__device__ __forceinline__ void cp_async_wait() {
    asm volatile("cp.async.wait_group %0;" :: "n"(N) : "memory");
}

__device__ __forceinline__ uint32_t lds32(uint32_t addr) {
    uint32_t v;
    asm volatile("ld.shared.b32 %0, [%1];" : "=r"(v) : "r"(addr));
    return v;
}

// fp16 HMMA with fp32 accumulation: D = A(16x16) * B(16x8)^T + D
__device__ __forceinline__ void mma_f16(float* c, const uint32_t* a, const uint32_t* b) {
    asm volatile(
        "mma.sync.aligned.m16n8k16.row.col.f32.f16.f16.f32 "
        "{%0,%1,%2,%3}, {%4,%5,%6,%7}, {%8,%9}, {%0,%1,%2,%3};"
        : "+f"(c[0]), "+f"(c[1]), "+f"(c[2]), "+f"(c[3])
        : "r"(a[0]), "r"(a[1]), "r"(a[2]), "r"(a[3]), "r"(b[0]), "r"(b[1]));
}

// ============================================================
// Kernel 1: per-block min/max partials over x  (+ dtype probe in block 0)
// The harness may promote the int8 weight tensor to int32/float32 on upload:
//  - int32 storage: every word is in [-128,127]
//  - float32 storage: every word as float is integral in [-128,127]
//  - else genuine packed int8
// ============================================================
__global__ void __launch_bounds__(256) k_minmax(const float4* __restrict__ x, int n4,
                                                const int* __restrict__ w) {
    __shared__ float smin[256], smax[256];
    int tid = threadIdx.x;

    if (blockIdx.x == 0) {          // dtype probe (4096 words, misclassify p ~ 2^-24/word)
        __shared__ int s_i32_ok, s_f32_ok;
        if (tid == 0) { s_i32_ok = 1; s_f32_ok = 1; }
        __syncthreads();
        int i32_ok = 1, f32_ok = 1;
        for (int i = tid; i < 4096; i += 256) {
            int v = w[i];
            if (v < -128 || v > 127) i32_ok = 0;
            float f = __int_as_float(v);
            if (!(f >= -128.0f && f <= 127.0f && rintf(f) == f)) f32_ok = 0;
        }
        if (!i32_ok) atomicAnd(&s_i32_ok, 0);
        if (!f32_ok) atomicAnd(&s_f32_ok, 0);
        __syncthreads();
        if (tid == 0) g_w_mode = s_i32_ok ? 1 : (s_f32_ok ? 2 : 0);
    }

    float mn = 0.0f, mx = 0.0f;  // min(.,0)/max(.,0) clamp folded in
    for (int i = blockIdx.x * 256 + tid; i < n4; i += 2048 * 256) {
        float4 v = x[i];
        mn = fminf(mn, fminf(fminf(v.x, v.y), fminf(v.z, v.w)));
        mx = fmaxf(mx, fmaxf(fmaxf(v.x, v.y), fmaxf(v.z, v.w)));
    }
    smin[tid] = mn; smax[tid] = mx;
    __syncthreads();
    for (int off = 128; off > 0; off >>= 1) {
        if (tid < off) {
            smin[tid] = fminf(smin[tid], smin[tid + off]);
            smax[tid] = fmaxf(smax[tid], smax[tid + off]);
        }
        __syncthreads();
    }
    if (tid == 0) { g_pmin[blockIdx.x] = smin[0]; g_pmax[blockIdx.x] = smax[0]; }
}

// ============================================================
// Kernel 2: transpose w [K,N] -> g_wth [N,K] as fp16 (dtype-agnostic read)
// ============================================================
__global__ void __launch_bounds__(256) k_transpose(const void* __restrict__ wraw) {
    __shared__ signed char t[32][33];
    const signed char* w8  = (const signed char*)wraw;
    const int*         w32 = (const int*)wraw;
    const float*       wf  = (const float*)wraw;
    int mode = g_w_mode;
    int tx = threadIdx.x, ty = threadIdx.y;
    int n0 = blockIdx.x * 32, k0 = blockIdx.y * 32;
    #pragma unroll
    for (int i = ty; i < 32; i += 8) {
        size_t idx = (size_t)(k0 + i) * NDIM + n0 + tx;
        signed char v;
        if (mode == 1)      v = (signed char)w32[idx];
        else if (mode == 2) v = (signed char)(int)wf[idx];
        else                v = w8[idx];
        t[i][tx] = v;
    }
    __syncthreads();
    #pragma unroll
    for (int i = ty; i < 32; i += 8)
        g_wth[(size_t)(n0 + i) * KDIM + k0 + tx] = __int2half_rn((int)t[tx][i]);
}

// ============================================================
// Kernel 3: reduce -> scale/zp + fused epilogue coefficients
// ============================================================
__global__ void __launch_bounds__(1024) k_scalars(const float* __restrict__ wsc,
                                                  const int* __restrict__ sums,
                                                  const float* __restrict__ bias) {
    __shared__ float smin[1024], smax[1024];
    __shared__ float s_scale, s_zp;
    int tid = threadIdx.x;
    smin[tid] = fminf(g_pmin[tid], g_pmin[tid + 1024]);
    smax[tid] = fmaxf(g_pmax[tid], g_pmax[tid + 1024]);
    __syncthreads();
    for (int off = 512; off > 0; off >>= 1) {
        if (tid < off) {
            smin[tid] = fminf(smin[tid], smin[tid + off]);
            smax[tid] = fmaxf(smax[tid], smax[tid + off]);
        }
        __syncthreads();
    }
    if (tid == 0) {
        const float EPSV = 1.1920928955078125e-07f;  // np.finfo(float32).eps
        float mn = smin[0], mx = smax[0];
        float scale = fmaxf((mx - mn) / 255.0f, EPSV);
        float zp = -128.0f - rintf(mn / scale);      // rintf == round-half-even
        zp = fminf(fmaxf(zp, -128.0f), 127.0f);
        s_scale = scale;
        s_zp = zp;
        g_inv_scale = 1.0f / scale;
        g_zp = zp;
    }
    __syncthreads();
    float alpha = s_scale * wsc[tid];
    g_alpha[tid] = alpha;
    g_beta[tid]  = fmaf(-alpha * s_zp, (float)sums[tid], bias[tid]);
}

// ============================================================
// Kernel 4: quantize x -> g_xqh (fp16 holding exact small ints)
// ============================================================
__global__ void __launch_bounds__(256) k_quant(const float4* __restrict__ x,
                                               uint2* __restrict__ xq, int n4) {
    float inv = g_inv_scale;
    float zp  = g_zp;
    for (int i = blockIdx.x * 256 + threadIdx.x; i < n4; i += 2048 * 256) {
        float4 v = x[i];
        float a = fminf(fmaxf(rintf(v.x * inv) + zp, -128.0f), 127.0f);
        float b = fminf(fmaxf(rintf(v.y * inv) + zp, -128.0f), 127.0f);
        float c = fminf(fmaxf(rintf(v.z * inv) + zp, -128.0f), 127.0f);
        float d = fminf(fmaxf(rintf(v.w * inv) + zp, -128.0f), 127.0f);
        __half2 lo = __floats2half2_rn(a, b);   // integral values: exact
        __half2 hi = __floats2half2_rn(c, d);
        uint2 q;
        q.x = *(uint32_t*)&lo;
        q.y = *(uint32_t*)&hi;
        xq[i] = q;
    }
}

// ============================================================
// Kernel 5: fp16 HMMA GEMM (mma.sync m16n8k16.f32) + fused dequant epilogue
//   8 warps: 2 (M) x 4 (N); warp tile 64x32; cp.async 4-stage pipeline
//   Register-lean: B frags (8 regs) per k16 slab; A frags (4) per mt.
// ============================================================
__device__ __forceinline__ void load_stage(uint32_t sb, int s, int m0, int n0, int k0e) {
    uint32_t base = sb + SM_TILES + s * STAGE_BYTES;
    int t = threadIdx.x;
    #pragma unroll
    for (int h = 0; h < 2; ++h) {
        int cc = t + h * 256;              // 0..511 chunk id
        int row = cc >> 2, kw = cc & 3;    // 128 rows x 4 x 16B (= 32 fp16/row)
        cp_async16(base + row * ROWB + kw * 16,
                   g_xqh + (size_t)(m0 + row) * KDIM + k0e + kw * 8);
    }
    #pragma unroll
    for (int h = 0; h < 2; ++h) {
        int cc = t + h * 256;
        int row = cc >> 2, kw = cc & 3;
        cp_async16(base + A_STG + row * ROWB + kw * 16,
                   g_wth + (size_t)(n0 + row) * KDIM + k0e + kw * 8);
    }
}

__global__ void __launch_bounds__(THREADS, 2) gemm_k(float* __restrict__ out) {
    extern __shared__ char smem[];
    uint32_t sb = smem_u32(smem);
    int tid = threadIdx.x, wid = tid >> 5, lane = tid & 31;
    int warpM = wid >> 2;             // 0..1  (64 rows each)
    int warpN = wid & 3;              // 0..3  (32 cols each)
    int ntile = blockIdx.x & 7;
    int mtile = blockIdx.x >> 3;
    int m0 = mtile * BM, n0 = ntile * BN;

    // cache epilogue coefficients
    float* aS = (float*)(smem + SM_ALPHA);
    float* bS = (float*)(smem + SM_BETA);
    for (int i = tid; i < BN; i += THREADS) {
        aS[i] = g_alpha[n0 + i];
        bS[i] = g_beta[n0 + i];
    }

    // prologue: fill STAGES-1 stages
    #pragma unroll
    for (int st = 0; st < STAGES - 1; ++st) {
        load_stage(sb, st, m0, n0, st * BKE);
        cp_async_commit();
    }

    float acc[4][4][4];
    #pragma unroll
    for (int mt = 0; mt < 4; ++mt)
        #pragma unroll
        for (int nt = 0; nt < 4; ++nt)
            #pragma unroll
            for (int r = 0; r < 4; ++r)
                acc[mt][nt][r] = 0.0f;

    int g = lane >> 2;                 // groupID 0..7
    int q = lane & 3;                  // threadID_in_group 0..3

    for (int it = 0; it < KITERS; ++it) {
        cp_async_wait<STAGES - 2>();
        __syncthreads();
        int s = it & (STAGES - 1);
        uint32_t a_base = sb + SM_TILES + s * STAGE_BYTES + (warpM * 64) * ROWB;
        uint32_t b_base = sb + SM_TILES + s * STAGE_BYTES + A_STG + (warpN * 32) * ROWB;

        #pragma unroll
        for (int kk = 0; kk < 2; ++kk) {       // two k16 slabs per BKE=32
            int ko = kk * 32 + q * 4;          // byte offset: k elem = kk*16 + q*2
            uint32_t bfr[4][2];
            #pragma unroll
            for (int nt = 0; nt < 4; ++nt) {
                uint32_t bd = b_base + (nt * 8 + g) * ROWB + ko;
                bfr[nt][0] = lds32(bd);                 // col g, k[2q,2q+1]
                bfr[nt][1] = lds32(bd + 16);            // col g, k[2q+8,2q+9]
            }
            #pragma unroll
            for (int mt = 0; mt < 4; ++mt) {
                uint32_t ad = a_base + (mt * 16 + g) * ROWB + ko;
                uint32_t af[4];
                af[0] = lds32(ad);                      // row g,   k lo
                af[1] = lds32(ad + 8 * ROWB);           // row g+8, k lo
                af[2] = lds32(ad + 16);                 // row g,   k hi
                af[3] = lds32(ad + 8 * ROWB + 16);      // row g+8, k hi
                #pragma unroll
                for (int nt = 0; nt < 4; ++nt)
                    mma_f16(acc[mt][nt], af, bfr[nt]);
            }
        }

        if (it + STAGES - 1 < KITERS)
            load_stage(sb, (it + STAGES - 1) & (STAGES - 1), m0, n0,
                       (it + STAGES - 1) * BKE);
        cp_async_commit();   // commit (possibly empty) to keep group counting uniform
    }

    // ---- epilogue: y = alpha[n]*acc + beta[n] ----
    #pragma unroll
    for (int mt = 0; mt < 4; ++mt) {
        int r0 = m0 + warpM * 64 + mt * 16 + g;
        float* out0 = out + (size_t)r0 * NDIM;
        float* out1 = out0 + (size_t)8 * NDIM;
        #pragma unroll
        for (int nt = 0; nt < 4; ++nt) {
            int cco = warpN * 32 + nt * 8 + q * 2;   // col within block
            int col = n0 + cco;
            float a0 = aS[cco], a1 = aS[cco + 1];
            float b0 = bS[cco], b1 = bS[cco + 1];
            float2 v0, v1;
            v0.x = fmaf(acc[mt][nt][0], a0, b0);
            v0.y = fmaf(acc[mt][nt][1], a1, b1);
            v1.x = fmaf(acc[mt][nt][2], a0, b0);
            v1.y = fmaf(acc[mt][nt][3], a1, b1);
            *(float2*)(out0 + col) = v0;
            *(float2*)(out1 + col) = v1;
        }
    }
}

// ============================================================
// Host launch
// ============================================================
extern "C" void kernel_launch(void* const* d_in, const int* in_sizes, int n_in,
                              void* d_out, int out_size) {
    const float* x    = (const float*)d_in[0];
    const void*  w    = d_in[1];
    const float* wsc  = (const float*)d_in[2];
    const int*   sums = (const int*)d_in[3];
    const float* bias = (const float*)d_in[4];
    float*       out  = (float*)d_out;

    cudaFuncSetAttribute(gemm_k, cudaFuncAttributeMaxDynamicSharedMemorySize,
                         SMEM_TOTAL);

    void* xq_ptr = nullptr;
    cudaGetSymbolAddress(&xq_ptr, g_xqh);

    int n4 = (MDIM * KDIM) / 4;
    k_minmax<<<2048, 256>>>((const float4*)x, n4, (const int*)w);
    k_transpose<<<dim3(NDIM / 32, KDIM / 32), dim3(32, 8)>>>(w);
    k_scalars<<<1, 1024>>>(wsc, sums, bias);
    k_quant<<<2048, 256>>>((const float4*)x, (uint2*)xq_ptr, n4);
    gemm_k<<<(MDIM / BM) * (NDIM / BN), THREADS, SMEM_TOTAL>>>(out);
}

// round 14
// speedup vs baseline: 3.0738x; 1.0243x over previous
#include <cuda_runtime.h>
#include <cuda_fp16.h>
#include <cstdint>

// ============================================================
// Problem constants
// ============================================================
#define MDIM 32768
#define KDIM 1024
#define NDIM 1024

static constexpr int BM = 128;
static constexpr int BN = 256;
static constexpr int BKE = 32;             // K elements (fp16) per stage = 64 B rows
static constexpr int STAGES = 4;
static constexpr int KITERS = KDIM / BKE;  // 32
static constexpr int THREADS = 256;

// padded smem rows: 64 data bytes padded to 80 (16B aligned; conflict-free for
// both LDS.32 and ldmatrix: rows r*80B hit banks 20r mod 32 -> 8-row x 16B
// ldmatrix phase covers all 32 banks exactly once)
static constexpr int ROWB = 80;
static constexpr int A_STG = BM * ROWB;            // 10240
static constexpr int B_STG = BN * ROWB;            // 20480
static constexpr int STAGE_BYTES = A_STG + B_STG;  // 30720
static constexpr int SM_ALPHA = 0;                 // 256 floats
static constexpr int SM_BETA  = 1024;              // 256 floats
static constexpr int SM_TILES = 2048;
static constexpr int SMEM_TOTAL = SM_TILES + STAGES * STAGE_BYTES;  // 124928

// ============================================================
// Device scratch (no allocations allowed)
// ============================================================
__device__ __align__(1024) __half g_xqh[(size_t)MDIM * KDIM];   // 64 MB quantized x (fp16 ints)
__device__ __align__(1024) __half g_wth[(size_t)NDIM * KDIM];   // 2 MB transposed weight [N,K]
__device__ float g_alpha[NDIM];
__device__ float g_beta[NDIM];
__device__ float g_pmin[2048];
__device__ float g_pmax[2048];
__device__ float g_inv_scale;
__device__ float g_zp;
__device__ int   g_w_mode;   // 0 = int8 storage, 1 = int32 storage, 2 = float32 storage

// ============================================================
// PTX helpers (baseline ISA only — harness targets compute_103, no tcgen05/TMA)
// ============================================================
__device__ __forceinline__ uint32_t smem_u32(const void* p) {
    uint32_t a;
    asm("{ .reg .u64 t; cvta.to.shared.u64 t, %1; cvt.u32.u64 %0, t; }"
        : "=r"(a) : "l"(p));
    return a;
}

__device__ __forceinline__ void cp_async16(uint32_t dst, const void* src) {
    asm volatile("cp.async.cg.shared.global [%0], [%1], 16;"
                 :: "r"(dst), "l"(src) : "memory");
}
__device__ __forceinline__ void cp_async_commit() {
    asm volatile("cp.async.commit_group;" ::: "memory");
}
template <int N>
__device__ __forceinline__ void cp_async_wait() {
    asm volatile("cp.async.wait_group %0;" :: "n"(N) : "memory");
}

// ldmatrix x4: four 8x8 b16 matrices, per-lane row addresses
__device__ __forceinline__ void ldsm_x4(uint32_t& r0, uint32_t& r1,
                                        uint32_t& r2, uint32_t& r3, uint32_t addr) {
    asm volatile("ldmatrix.sync.aligned.m8n8.x4.shared.b16 {%0,%1,%2,%3}, [%4];"
                 : "=r"(r0), "=r"(r1), "=r"(r2), "=r"(r3) : "r"(addr));
}

// fp16 HMMA with fp32 accumulation: D = A(16x16) * B(16x8)^T + D
__device__ __forceinline__ void mma_f16(float* c, const uint32_t* a, const uint32_t* b) {
    asm volatile(
        "mma.sync.aligned.m16n8k16.row.col.f32.f16.f16.f32 "
        "{%0,%1,%2,%3}, {%4,%5,%6,%7}, {%8,%9}, {%0,%1,%2,%3};"
        : "+f"(c[0]), "+f"(c[1]), "+f"(c[2]), "+f"(c[3])
        : "r"(a[0]), "r"(a[1]), "r"(a[2]), "r"(a[3]), "r"(b[0]), "r"(b[1]));
}

// ============================================================
// Kernel 1: per-block min/max partials over x  (+ dtype probe in block 0)
// ============================================================
__global__ void __launch_bounds__(256) k_minmax(const float4* __restrict__ x, int n4,
                                                const int* __restrict__ w) {
    __shared__ float smin[256], smax[256];
    int tid = threadIdx.x;

    if (blockIdx.x == 0) {          // dtype probe (4096 words, misclassify p ~ 2^-24/word)
        __shared__ int s_i32_ok, s_f32_ok;
        if (tid == 0) { s_i32_ok = 1; s_f32_ok = 1; }
        __syncthreads();
        int i32_ok = 1, f32_ok = 1;
        for (int i = tid; i < 4096; i += 256) {
            int v = w[i];
            if (v < -128 || v > 127) i32_ok = 0;
            float f = __int_as_float(v);
            if (!(f >= -128.0f && f <= 127.0f && rintf(f) == f)) f32_ok = 0;
        }
        if (!i32_ok) atomicAnd(&s_i32_ok, 0);
        if (!f32_ok) atomicAnd(&s_f32_ok, 0);
        __syncthreads();
        if (tid == 0) g_w_mode = s_i32_ok ? 1 : (s_f32_ok ? 2 : 0);
    }

    float mn = 0.0f, mx = 0.0f;  // min(.,0)/max(.,0) clamp folded in
    for (int i = blockIdx.x * 256 + tid; i < n4; i += 2048 * 256) {
        float4 v = x[i];
        mn = fminf(mn, fminf(fminf(v.x, v.y), fminf(v.z, v.w)));
        mx = fmaxf(mx, fmaxf(fmaxf(v.x, v.y), fmaxf(v.z, v.w)));
    }
    smin[tid] = mn; smax[tid] = mx;
    __syncthreads();
    for (int off = 128; off > 0; off >>= 1) {
        if (tid < off) {
            smin[tid] = fminf(smin[tid], smin[tid + off]);
            smax[tid] = fmaxf(smax[tid], smax[tid + off]);
        }
        __syncthreads();
    }
    if (tid == 0) { g_pmin[blockIdx.x] = smin[0]; g_pmax[blockIdx.x] = smax[0]; }
}

// ============================================================
// Kernel 2: transpose w [K,N] -> g_wth [N,K] as fp16 (dtype-agnostic read)
// ============================================================
__global__ void __launch_bounds__(256) k_transpose(const void* __restrict__ wraw) {
    __shared__ signed char t[32][33];
    const signed char* w8  = (const signed char*)wraw;
    const int*         w32 = (const int*)wraw;
    const float*       wf  = (const float*)wraw;
    int mode = g_w_mode;
    int tx = threadIdx.x, ty = threadIdx.y;
    int n0 = blockIdx.x * 32, k0 = blockIdx.y * 32;
    #pragma unroll
    for (int i = ty; i < 32; i += 8) {
        size_t idx = (size_t)(k0 + i) * NDIM + n0 + tx;
        signed char v;
        if (mode == 1)      v = (signed char)w32[idx];
        else if (mode == 2) v = (signed char)(int)wf[idx];
        else                v = w8[idx];
        t[i][tx] = v;
    }
    __syncthreads();
    #pragma unroll
    for (int i = ty; i < 32; i += 8)
        g_wth[(size_t)(n0 + i) * KDIM + k0 + tx] = __int2half_rn((int)t[tx][i]);
}

// ============================================================
// Kernel 3: reduce -> scale/zp + fused epilogue coefficients
// ============================================================
__global__ void __launch_bounds__(1024) k_scalars(const float* __restrict__ wsc,
                                                  const int* __restrict__ sums,
                                                  const float* __restrict__ bias) {
    __shared__ float smin[1024], smax[1024];
    __shared__ float s_scale, s_zp;
    int tid = threadIdx.x;
    smin[tid] = fminf(g_pmin[tid], g_pmin[tid + 1024]);
    smax[tid] = fmaxf(g_pmax[tid], g_pmax[tid + 1024]);
    __syncthreads();
    for (int off = 512; off > 0; off >>= 1) {
        if (tid < off) {
            smin[tid] = fminf(smin[tid], smin[tid + off]);
            smax[tid] = fmaxf(smax[tid], smax[tid + off]);
        }
        __syncthreads();
    }
    if (tid == 0) {
        const float EPSV = 1.1920928955078125e-07f;  // np.finfo(float32).eps
        float mn = smin[0], mx = smax[0];
        float scale = fmaxf((mx - mn) / 255.0f, EPSV);
        float zp = -128.0f - rintf(mn / scale);      // rintf == round-half-even
        zp = fminf(fmaxf(zp, -128.0f), 127.0f);
        s_scale = scale;
        s_zp = zp;
        g_inv_scale = 1.0f / scale;
        g_zp = zp;
    }
    __syncthreads();
    float alpha = s_scale * wsc[tid];
    g_alpha[tid] = alpha;
    g_beta[tid]  = fmaf(-alpha * s_zp, (float)sums[tid], bias[tid]);
}

// ============================================================
// Kernel 4: quantize x -> g_xqh (fp16 holding exact small ints)
// ============================================================
__global__ void __launch_bounds__(256) k_quant(const float4* __restrict__ x,
                                               uint2* __restrict__ xq, int n4) {
    float inv = g_inv_scale;
    float zp  = g_zp;
    for (int i = blockIdx.x * 256 + threadIdx.x; i < n4; i += 2048 * 256) {
        float4 v = x[i];
        float a = fminf(fmaxf(rintf(v.x * inv) + zp, -128.0f), 127.0f);
        float b = fminf(fmaxf(rintf(v.y * inv) + zp, -128.0f), 127.0f);
        float c = fminf(fmaxf(rintf(v.z * inv) + zp, -128.0f), 127.0f);
        float d = fminf(fmaxf(rintf(v.w * inv) + zp, -128.0f), 127.0f);
        __half2 lo = __floats2half2_rn(a, b);   // integral values: exact
        __half2 hi = __floats2half2_rn(c, d);
        uint2 q;
        q.x = *(uint32_t*)&lo;
        q.y = *(uint32_t*)&hi;
        xq[i] = q;
    }
}

// ============================================================
// Kernel 5: fp16 HMMA GEMM, CTA 128x256, warp tile 64x64 (2Mx4N warps)
//   ldmatrix.x4 fragment loads; cp.async 4-stage pipeline; occ 1.
// ============================================================
__device__ __forceinline__ void load_stage(uint32_t sb, int s, int m0, int n0, int k0e) {
    uint32_t base = sb + SM_TILES + s * STAGE_BYTES;
    int t = threadIdx.x;
    #pragma unroll
    for (int h = 0; h < 2; ++h) {                  // A: 128 rows x 4 chunks
        int cc = t + h * 256;
        int row = cc >> 2, kw = cc & 3;
        cp_async16(base + row * ROWB + kw * 16,
                   g_xqh + (size_t)(m0 + row) * KDIM + k0e + kw * 8);
    }
    #pragma unroll
    for (int h = 0; h < 4; ++h) {                  // B: 256 rows x 4 chunks
        int cc = t + h * 256;
        int row = cc >> 2, kw = cc & 3;
        cp_async16(base + A_STG + row * ROWB + kw * 16,
                   g_wth + (size_t)(n0 + row) * KDIM + k0e + kw * 8);
    }
}

__global__ void __launch_bounds__(THREADS, 1) gemm_k(float* __restrict__ out) {
    extern __shared__ char smem[];
    uint32_t sb = smem_u32(smem);
    int tid = threadIdx.x, wid = tid >> 5, lane = tid & 31;
    int warpM = wid >> 2;             // 0..1  (64 rows each)
    int warpN = wid & 3;              // 0..3  (64 cols each)
    int ntile = blockIdx.x & 3;       // consecutive bids share the A tile (L2 reuse)
    int mtile = blockIdx.x >> 2;
    int m0 = mtile * BM, n0 = ntile * BN;

    // cache epilogue coefficients
    float* aS = (float*)(smem + SM_ALPHA);
    float* bS = (float*)(smem + SM_BETA);
    for (int i = tid; i < BN; i += THREADS) {
        aS[i] = g_alpha[n0 + i];
        bS[i] = g_beta[n0 + i];
    }

    // prologue: fill STAGES-1 stages
    #pragma unroll
    for (int st = 0; st < STAGES - 1; ++st) {
        load_stage(sb, st, m0, n0, st * BKE);
        cp_async_commit();
    }

    float acc[4][8][4];
    #pragma unroll
    for (int mt = 0; mt < 4; ++mt)
        #pragma unroll
        for (int nt = 0; nt < 8; ++nt)
            #pragma unroll
            for (int r = 0; r < 4; ++r)
                acc[mt][nt][r] = 0.0f;

    int g = lane >> 2;                 // groupID 0..7
    int q = lane & 3;                  // threadID_in_group 0..3
    int sub = lane >> 3, rr = lane & 7;
    // A ldmatrix lane offset: matrices {rows 0-7 klo, rows 8-15 klo, rows 0-7 khi, rows 8-15 khi}
    uint32_t aoff = (uint32_t)(((sub & 1) * 8 + rr) * ROWB + (sub >> 1) * 16);
    // B ldmatrix lane offset: matrices {n0-7 klo, n0-7 khi, n8-15 klo, n8-15 khi}
    uint32_t boff = (uint32_t)(((sub >> 1) * 8 + rr) * ROWB + (sub & 1) * 16);

    for (int it = 0; it < KITERS; ++it) {
        cp_async_wait<STAGES - 2>();
        __syncthreads();
        int s = it & (STAGES - 1);
        uint32_t a_base = sb + SM_TILES + s * STAGE_BYTES + (warpM * 64) * ROWB + aoff;
        uint32_t b_base = sb + SM_TILES + s * STAGE_BYTES + A_STG + (warpN * 64) * ROWB + boff;

        #pragma unroll
        for (int kk = 0; kk < 2; ++kk) {       // two k16 slabs per BKE=32
            uint32_t bfr[8][2];
            #pragma unroll
            for (int nt2 = 0; nt2 < 4; ++nt2)  // each x4 covers two n8 tiles
                ldsm_x4(bfr[2 * nt2][0], bfr[2 * nt2][1],
                        bfr[2 * nt2 + 1][0], bfr[2 * nt2 + 1][1],
                        b_base + nt2 * 16 * ROWB + kk * 32);
            #pragma unroll
            for (int mt = 0; mt < 4; ++mt) {
                uint32_t af[4];
                ldsm_x4(af[0], af[1], af[2], af[3],
                        a_base + mt * 16 * ROWB + kk * 32);
                #pragma unroll
                for (int nt = 0; nt < 8; ++nt)
                    mma_f16(acc[mt][nt], af, bfr[nt]);
            }
        }

        if (it + STAGES - 1 < KITERS)
            load_stage(sb, (it + STAGES - 1) & (STAGES - 1), m0, n0,
                       (it + STAGES - 1) * BKE);
        cp_async_commit();   // uniform group counting
    }

    // ---- epilogue: y = alpha[n]*acc + beta[n] ----
    #pragma unroll
    for (int mt = 0; mt < 4; ++mt) {
        int r0 = m0 + warpM * 64 + mt * 16 + g;
        float* out0 = out + (size_t)r0 * NDIM;
        float* out1 = out0 + (size_t)8 * NDIM;
        #pragma unroll
        for (int nt = 0; nt < 8; ++nt) {
            int cco = warpN * 64 + nt * 8 + q * 2;   // col within block
            int col = n0 + cco;
            float a0 = aS[cco], a1 = aS[cco + 1];
            float b0 = bS[cco], b1 = bS[cco + 1];
            float2 v0, v1;
            v0.x = fmaf(acc[mt][nt][0], a0, b0);
            v0.y = fmaf(acc[mt][nt][1], a1, b1);
            v1.x = fmaf(acc[mt][nt][2], a0, b0);
            v1.y = fmaf(acc[mt][nt][3], a1, b1);
            *(float2*)(out0 + col) = v0;
            *(float2*)(out1 + col) = v1;
        }
    }
}

// ============================================================
// Host launch
// ============================================================
extern "C" void kernel_launch(void* const* d_in, const int* in_sizes, int n_in,
                              void* d_out, int out_size) {
    const float* x    = (const float*)d_in[0];
    const void*  w    = d_in[1];
    const float* wsc  = (const float*)d_in[2];
    const int*   sums = (const int*)d_in[3];
    const float* bias = (const float*)d_in[4];
    float*       out  = (float*)d_out;

    cudaFuncSetAttribute(gemm_k, cudaFuncAttributeMaxDynamicSharedMemorySize,
                         SMEM_TOTAL);

    void* xq_ptr = nullptr;
    cudaGetSymbolAddress(&xq_ptr, g_xqh);

    int n4 = (MDIM * KDIM) / 4;
    k_minmax<<<2048, 256>>>((const float4*)x, n4, (const int*)w);
    k_transpose<<<dim3(NDIM / 32, KDIM / 32), dim3(32, 8)>>>(w);
    k_scalars<<<1, 1024>>>(wsc, sums, bias);
    k_quant<<<2048, 256>>>((const float4*)x, (uint2*)xq_ptr, n4);
    gemm_k<<<(MDIM / BM) * (NDIM / BN), THREADS, SMEM_TOTAL>>>(out);
}